// round 1
// baseline (speedup 1.0000x reference)
#include <cuda_runtime.h>
#include <math.h>
#include <stdint.h>

// Problem dims
#define BSZ     2
#define LSEQ    2048
#define DMODEL  2048
#define INTER   4096
#define NHEADS  64
#define PDIM    64
#define NSTATE  128
#define KCONV   4
#define CONV_DIM (INTER + 2*NSTATE)   // 4352
#define TOKENS  (BSZ*LSEQ)            // 4096
#define EPS     1e-5f

// ---------------- scratch (device globals; no allocation allowed) ----------
__device__ float g_gate[TOKENS*INTER];      // hs @ W_z
__device__ float g_xBC[TOKENS*CONV_DIM];    // hs @ W_xBC (pre-conv)
__device__ float g_xBCc[TOKENS*CONV_DIM];   // post conv+silu
__device__ float g_dt[TOKENS*NHEADS];       // hs @ W_dt (raw, pre-softplus)
__device__ float g_y[TOKENS*INTER];         // scan output
__device__ float g_norm[TOKENS*INTER];      // gated rmsnorm output

// ---------------- SGEMM: C[M,N] = A[M,K] @ B[K,N], row-major ---------------
// M % 128 == 0, K % 16 == 0, N % 4 == 0 (N guarded vs 128-tile).
__global__ void __launch_bounds__(256) sgemm_kernel(
    const float* __restrict__ A, const float* __restrict__ B,
    float* __restrict__ C, int M, int N, int Kdim)
{
    const int BM = 128, BN = 128, BK = 16, TM = 8, TN = 8;
    __shared__ float As[BM][BK];   // natural layout (float4 stores, scalar bc reads)
    __shared__ float Bs[BK][BN];

    int tid  = threadIdx.x;
    int brow = blockIdx.y * BM;
    int bcol = blockIdx.x * BN;
    int tx = tid & 15, ty = tid >> 4;
    int trow = ty * TM, tcol = tx * TN;

    float acc[TM][TN];
    #pragma unroll
    for (int i = 0; i < TM; i++)
        #pragma unroll
        for (int j = 0; j < TN; j++) acc[i][j] = 0.f;

    for (int k0 = 0; k0 < Kdim; k0 += BK) {
        // load A tile: 512 float4, 2 per thread
        #pragma unroll
        for (int j = 0; j < 2; j++) {
            int i   = tid + j * 256;
            int ar  = i >> 2;          // row in tile
            int ac4 = i & 3;           // float4 col (k)
            const float4 av = *(const float4*)&A[(size_t)(brow + ar) * Kdim + k0 + ac4*4];
            *(float4*)&As[ar][ac4*4] = av;
        }
        // load B tile: 512 float4, 2 per thread, guard N
        #pragma unroll
        for (int j = 0; j < 2; j++) {
            int i   = tid + j * 256;
            int br  = i >> 5;          // k row
            int bc4 = i & 31;          // float4 col (n)
            int gcol = bcol + bc4*4;
            float4 bv = make_float4(0.f,0.f,0.f,0.f);
            if (gcol < N)
                bv = *(const float4*)&B[(size_t)(k0 + br) * N + gcol];
            *(float4*)&Bs[br][bc4*4] = bv;
        }
        __syncthreads();

        #pragma unroll
        for (int kk = 0; kk < BK; kk++) {
            float a_frag[TM], b_frag[TN];
            #pragma unroll
            for (int i = 0; i < TM; i++) a_frag[i] = As[trow + i][kk];
            float4 b0 = *(float4*)&Bs[kk][tcol];
            float4 b1 = *(float4*)&Bs[kk][tcol + 4];
            b_frag[0]=b0.x; b_frag[1]=b0.y; b_frag[2]=b0.z; b_frag[3]=b0.w;
            b_frag[4]=b1.x; b_frag[5]=b1.y; b_frag[6]=b1.z; b_frag[7]=b1.w;
            #pragma unroll
            for (int i = 0; i < TM; i++)
                #pragma unroll
                for (int j = 0; j < TN; j++)
                    acc[i][j] = fmaf(a_frag[i], b_frag[j], acc[i][j]);
        }
        __syncthreads();
    }

    #pragma unroll
    for (int i = 0; i < TM; i++) {
        int row = brow + trow + i;
        #pragma unroll
        for (int j4 = 0; j4 < 2; j4++) {
            int col = bcol + tcol + j4*4;
            if (col < N) {
                float4 v = make_float4(acc[i][j4*4+0], acc[i][j4*4+1],
                                       acc[i][j4*4+2], acc[i][j4*4+3]);
                *(float4*)&C[(size_t)row * N + col] = v;
            }
        }
    }
}

// ---------------- causal depthwise conv1d (K=4) + bias + silu --------------
__global__ void __launch_bounds__(256) conv_silu_kernel(
    const float* __restrict__ conv_w, const float* __restrict__ conv_b)
{
    int idx = blockIdx.x * 256 + threadIdx.x;          // over TOKENS*CONV_DIM
    int c  = idx % CONV_DIM;
    int bt = idx / CONV_DIM;                           // flat (b,t)
    int t  = bt & (LSEQ - 1);

    float acc = conv_b[c];
    #pragma unroll
    for (int k = 0; k < KCONV; k++) {
        int tt = t - (KCONV - 1) + k;
        if (tt >= 0) {
            float xv = g_xBC[(size_t)(bt - (KCONV - 1) + k) * CONV_DIM + c];
            acc = fmaf(xv, conv_w[c * KCONV + k], acc);
        }
    }
    // silu
    float s = acc / (1.f + expf(-acc));
    g_xBCc[idx] = s;
}

// ---------------- sequential SSM scan: one CTA per (b, head) ---------------
// 256 threads: tid -> p = tid/4 (0..63), q = tid%4; each thread owns
// state[p, n] for n = i*4 + q, i in [0,32).
__global__ void __launch_bounds__(256) scan_kernel(
    const float* __restrict__ dt_bias, const float* __restrict__ A_log,
    const float* __restrict__ Dvec)
{
    int b = blockIdx.x >> 6;
    int h = blockIdx.x & 63;
    int tid = threadIdx.x;
    int p = tid >> 2, q = tid & 3;

    float state[32];
    #pragma unroll
    for (int i = 0; i < 32; i++) state[i] = 0.f;

    const float Ah   = -expf(A_log[h]);
    const float bias = dt_bias[h];
    const float Dh   = Dvec[h];

    __shared__ float sx[2][64];
    __shared__ float sBC[2][256];   // [0:128)=B, [128:256)=C

    const float* xrow_base = g_xBCc + (size_t)b * LSEQ * CONV_DIM;
    const float* dt_base   = g_dt   + (size_t)b * LSEQ * NHEADS + h;
    float*       y_base    = g_y    + (size_t)b * LSEQ * INTER + h * PDIM;

    // prefetch t = 0
    float rx = 0.f, rbc, rdt;
    {
        const float* row = xrow_base;
        if (tid < 64) rx = row[h * PDIM + tid];
        rbc = row[INTER + tid];
        rdt = dt_base[0];
    }

    for (int t = 0; t < LSEQ; t++) {
        int buf = t & 1;
        if (tid < 64) sx[buf][tid] = rx;
        sBC[buf][tid] = rbc;
        float dtv = rdt;
        __syncthreads();

        // prefetch t+1 (overlaps with compute below)
        if (t + 1 < LSEQ) {
            const float* row = xrow_base + (size_t)(t + 1) * CONV_DIM;
            if (tid < 64) rx = row[h * PDIM + tid];
            rbc = row[INTER + tid];
            rdt = dt_base[(size_t)(t + 1) * NHEADS];
        }

        float xdt = dtv + bias;
        float sp  = (xdt < 10.f) ? log1pf(expf(xdt)) : xdt;   // softplus_thresh
        float dA  = expf(sp * Ah);
        float xv  = sx[buf][p];
        float dtx = sp * xv;

        const float* Bp = sBC[buf];
        const float* Cp = sBC[buf] + 128;
        float accv = 0.f;
        #pragma unroll
        for (int i = 0; i < 32; i++) {
            int n = i * 4 + q;
            float s = fmaf(state[i], dA, dtx * Bp[n]);
            state[i] = s;
            accv = fmaf(s, Cp[n], accv);
        }
        // reduce across the 4 q-lanes (consecutive in warp)
        accv += __shfl_xor_sync(0xffffffffu, accv, 1);
        accv += __shfl_xor_sync(0xffffffffu, accv, 2);
        if (q == 0)
            y_base[(size_t)t * INTER + p] = fmaf(Dh, xv, accv);
        // double-buffered shared: single barrier per step is sufficient
    }
}

// ---------------- gated RMSNorm (G=1 -> norm over full 4096) ---------------
__global__ void __launch_bounds__(256) norm_kernel(const float* __restrict__ norm_w)
{
    int tok = blockIdx.x;
    __shared__ float sh[INTER];          // 16 KB
    __shared__ float sred[8];
    __shared__ float s_scale;

    const float* yrow = g_y    + (size_t)tok * INTER;
    const float* grow = g_gate + (size_t)tok * INTER;

    float ss = 0.f;
    for (int i = threadIdx.x; i < INTER; i += 256) {
        float g  = grow[i];
        float sg = g / (1.f + expf(-g));     // silu(gate)
        float hh = yrow[i] * sg;
        sh[i] = hh;
        ss = fmaf(hh, hh, ss);
    }
    #pragma unroll
    for (int o = 16; o; o >>= 1) ss += __shfl_xor_sync(0xffffffffu, ss, o);
    if ((threadIdx.x & 31) == 0) sred[threadIdx.x >> 5] = ss;
    __syncthreads();
    if (threadIdx.x == 0) {
        float tot = 0.f;
        #pragma unroll
        for (int j = 0; j < 8; j++) tot += sred[j];
        s_scale = rsqrtf(tot * (1.f / INTER) + EPS);
    }
    __syncthreads();
    float r = s_scale;
    for (int i = threadIdx.x; i < INTER; i += 256)
        g_norm[(size_t)tok * INTER + i] = sh[i] * r * norm_w[i];
}

// ---------------- launch ---------------------------------------------------
extern "C" void kernel_launch(void* const* d_in, const int* in_sizes, int n_in,
                              void* d_out, int out_size)
{
    const float* hs      = (const float*)d_in[0];   // [2,2048,2048]
    const float* W_z     = (const float*)d_in[1];   // [2048,4096]
    const float* W_xBC   = (const float*)d_in[2];   // [2048,4352]
    const float* W_dt    = (const float*)d_in[3];   // [2048,64]
    const float* conv_w  = (const float*)d_in[4];   // [4352,4]
    const float* conv_b  = (const float*)d_in[5];   // [4352]
    const float* dt_bias = (const float*)d_in[6];   // [64]
    const float* A_log   = (const float*)d_in[7];   // [64]
    const float* Dv      = (const float*)d_in[8];   // [64]
    const float* norm_w  = (const float*)d_in[9];   // [4096]
    const float* W_out   = (const float*)d_in[10];  // [4096,2048]
    float* out = (float*)d_out;

    float *p_gate, *p_xBC, *p_dt, *p_norm;
    cudaGetSymbolAddress((void**)&p_gate, g_gate);
    cudaGetSymbolAddress((void**)&p_xBC,  g_xBC);
    cudaGetSymbolAddress((void**)&p_dt,   g_dt);
    cudaGetSymbolAddress((void**)&p_norm, g_norm);

    // 1) input projections
    {
        dim3 gz(INTER/128, TOKENS/128);
        sgemm_kernel<<<gz, 256>>>(hs, W_z, p_gate, TOKENS, INTER, DMODEL);
        dim3 gx(CONV_DIM/128, TOKENS/128);
        sgemm_kernel<<<gx, 256>>>(hs, W_xBC, p_xBC, TOKENS, CONV_DIM, DMODEL);
        dim3 gd(1, TOKENS/128);
        sgemm_kernel<<<gd, 256>>>(hs, W_dt, p_dt, TOKENS, NHEADS, DMODEL);
    }
    // 2) causal conv + silu
    conv_silu_kernel<<<(TOKENS*CONV_DIM)/256, 256>>>(conv_w, conv_b);
    // 3) SSM scan
    scan_kernel<<<BSZ*NHEADS, 256>>>(dt_bias, A_log, Dv);
    // 4) gated RMSNorm
    norm_kernel<<<TOKENS, 256>>>(norm_w);
    // 5) output projection
    {
        dim3 go(DMODEL/128, TOKENS/128);
        sgemm_kernel<<<go, 256>>>(p_norm, W_out, out, TOKENS, DMODEL, INTER);
    }
}

// round 3
// speedup vs baseline: 1.9429x; 1.9429x over previous
#include <cuda_runtime.h>
#include <cuda_bf16.h>
#include <math.h>
#include <stdint.h>

// Problem dims
#define BSZ     2
#define LSEQ    2048
#define DMODEL  2048
#define INTER   4096
#define NHEADS  64
#define PDIM    64
#define NSTATE  128
#define KCONV   4
#define CONV_DIM (INTER + 2*NSTATE)   // 4352
#define TOKENS  (BSZ*LSEQ)            // 4096
#define EPS     1e-5f

// ---------------- scratch (device globals; no allocation allowed) ----------
__device__ __align__(16) float g_gate[TOKENS*INTER];
__device__ __align__(16) float g_xBC[TOKENS*CONV_DIM];
__device__ __align__(16) float g_xBCc[TOKENS*CONV_DIM];
__device__ __align__(16) float g_dt[TOKENS*NHEADS];
__device__ __align__(16) float g_y[TOKENS*INTER];

// split-bf16 operands for tensor-core GEMMs
__device__ __align__(16) __nv_bfloat16 g_hs_hi[TOKENS*DMODEL];
__device__ __align__(16) __nv_bfloat16 g_hs_lo[TOKENS*DMODEL];
__device__ __align__(16) __nv_bfloat16 g_Wz_hi[INTER*DMODEL];     // transposed [N,K]
__device__ __align__(16) __nv_bfloat16 g_Wz_lo[INTER*DMODEL];
__device__ __align__(16) __nv_bfloat16 g_WxBC_hi[CONV_DIM*DMODEL];
__device__ __align__(16) __nv_bfloat16 g_WxBC_lo[CONV_DIM*DMODEL];
__device__ __align__(16) __nv_bfloat16 g_Wout_hi[DMODEL*INTER];
__device__ __align__(16) __nv_bfloat16 g_Wout_lo[DMODEL*INTER];
__device__ __align__(16) __nv_bfloat16 g_norm_hi[TOKENS*INTER];
__device__ __align__(16) __nv_bfloat16 g_norm_lo[TOKENS*INTER];

// ---------------- PTX helpers ----------------------------------------------
__device__ __forceinline__ uint32_t smem_u32(const void* p) {
    uint32_t a;
    asm("{ .reg .u64 t; cvta.to.shared.u64 t, %1; cvt.u32.u64 %0, t; }"
        : "=r"(a) : "l"(p));
    return a;
}
__device__ __forceinline__ void cp16(uint32_t dst, const void* src) {
    asm volatile("cp.async.cg.shared.global [%0], [%1], 16;"
                 :: "r"(dst), "l"(src) : "memory");
}
__device__ __forceinline__ void cp_commit() {
    asm volatile("cp.async.commit_group;" ::: "memory");
}
template<int PENDING>
__device__ __forceinline__ void cp_wait() {
    asm volatile("cp.async.wait_group %0;" :: "n"(PENDING) : "memory");
}
__device__ __forceinline__ void ldm_x4(uint32_t addr, uint32_t* r) {
    asm volatile("ldmatrix.sync.aligned.m8n8.x4.shared.b16 {%0,%1,%2,%3}, [%4];"
                 : "=r"(r[0]), "=r"(r[1]), "=r"(r[2]), "=r"(r[3]) : "r"(addr));
}
__device__ __forceinline__ void mma_bf16(float* c, const uint32_t* a, const uint32_t* b) {
    asm volatile(
        "mma.sync.aligned.m16n8k16.row.col.f32.bf16.bf16.f32 "
        "{%0,%1,%2,%3}, {%4,%5,%6,%7}, {%8,%9}, {%0,%1,%2,%3};"
        : "+f"(c[0]), "+f"(c[1]), "+f"(c[2]), "+f"(c[3])
        : "r"(a[0]), "r"(a[1]), "r"(a[2]), "r"(a[3]), "r"(b[0]), "r"(b[1]));
}

// ---------------- HMMA GEMM: C[M,N] = A[M,K] @ Bt[N,K]^T -------------------
// A, Bt split bf16 (hi, lo); computes HH + HL + LH in fp32 accumulators.
// M, N multiples of 128; K multiple of 64.
__global__ void __launch_bounds__(256) gemm_mma(
    const __nv_bfloat16* __restrict__ Ahi, const __nv_bfloat16* __restrict__ Alo,
    const __nv_bfloat16* __restrict__ Bhi, const __nv_bfloat16* __restrict__ Blo,
    float* __restrict__ C, int M, int N, int K)
{
    extern __shared__ char smem[];
    uint32_t sbase = smem_u32(smem);
    const int TB = 16384;              // one 128x64 bf16 tile (128B rows, SW128)
    const int STAGE = 4 * TB;          // Ahi, Alo, Bhi, Blo

    int tid = threadIdx.x;
    int lane = tid & 31, wid = tid >> 5;
    int wm = wid & 3, wn = wid >> 2;   // warp tile: 32 x 64
    int brow = blockIdx.y * 128, bcol = blockIdx.x * 128;

    const __nv_bfloat16* src0 = Ahi + (size_t)brow * K;
    const __nv_bfloat16* src1 = Alo + (size_t)brow * K;
    const __nv_bfloat16* src2 = Bhi + (size_t)bcol * K;
    const __nv_bfloat16* src3 = Blo + (size_t)bcol * K;
    int nch = K >> 6;

    // --- async stage loader ---
    auto issue = [&](int ch) {
        uint32_t stage = sbase + (uint32_t)(ch & 1) * STAGE;
        const __nv_bfloat16* srcs[4] = {src0, src1, src2, src3};
        #pragma unroll
        for (int t = 0; t < 4; t++) {
            const __nv_bfloat16* P = srcs[t];
            uint32_t tb = stage + (uint32_t)t * TB;
            #pragma unroll
            for (int i = 0; i < 4; i++) {
                int c = tid + i * 256;          // 0..1023 16B chunks
                int row = c >> 3, u = c & 7;
                uint32_t dst = tb + (uint32_t)(row * 128 + ((u ^ (row & 7)) << 4));
                cp16(dst, P + (size_t)row * K + (size_t)ch * 64 + u * 8);
            }
        }
        cp_commit();
    };

    float acc[2][8][4];
    #pragma unroll
    for (int mf = 0; mf < 2; mf++)
        #pragma unroll
        for (int nf = 0; nf < 8; nf++)
            #pragma unroll
            for (int j = 0; j < 4; j++) acc[mf][nf][j] = 0.f;

    issue(0);
    issue(1);

    for (int ch = 0; ch < nch; ch++) {
        if (ch + 1 < nch) cp_wait<1>(); else cp_wait<0>();
        __syncthreads();
        uint32_t stage = sbase + (uint32_t)(ch & 1) * STAGE;

        #pragma unroll
        for (int ks = 0; ks < 4; ks++) {
            uint32_t aH[2][4], aL[2][4];
            #pragma unroll
            for (int mf = 0; mf < 2; mf++) {
                int row = wm * 32 + mf * 16 + (lane & 7) + ((lane >> 3) & 1) * 8;
                int u   = ks * 2 + ((lane >> 4) & 1);
                uint32_t off = (uint32_t)(row * 128 + ((u ^ (row & 7)) << 4));
                ldm_x4(stage + 0 * TB + off, aH[mf]);
                ldm_x4(stage + 1 * TB + off, aL[mf]);
            }
            uint32_t bH[8][2], bL[8][2];
            #pragma unroll
            for (int ng = 0; ng < 4; ng++) {
                int row = wn * 64 + ng * 16 + (lane & 7) + ((lane >> 4) & 1) * 8;
                int u   = ks * 2 + ((lane >> 3) & 1);
                uint32_t off = (uint32_t)(row * 128 + ((u ^ (row & 7)) << 4));
                uint32_t rH[4], rL[4];
                ldm_x4(stage + 2 * TB + off, rH);
                ldm_x4(stage + 3 * TB + off, rL);
                bH[2*ng][0] = rH[0]; bH[2*ng][1] = rH[1];
                bH[2*ng+1][0] = rH[2]; bH[2*ng+1][1] = rH[3];
                bL[2*ng][0] = rL[0]; bL[2*ng][1] = rL[1];
                bL[2*ng+1][0] = rL[2]; bL[2*ng+1][1] = rL[3];
            }
            #pragma unroll
            for (int mf = 0; mf < 2; mf++)
                #pragma unroll
                for (int nf = 0; nf < 8; nf++) {
                    mma_bf16(acc[mf][nf], aH[mf], bH[nf]);
                    mma_bf16(acc[mf][nf], aH[mf], bL[nf]);
                    mma_bf16(acc[mf][nf], aL[mf], bH[nf]);
                }
        }
        __syncthreads();
        if (ch + 2 < nch) issue(ch + 2);
    }

    // epilogue: c0,c1 = (r, c..c+1); c2,c3 = (r+8, c..c+1)
    #pragma unroll
    for (int mf = 0; mf < 2; mf++) {
        int row = brow + wm * 32 + mf * 16 + (lane >> 2);
        #pragma unroll
        for (int nf = 0; nf < 8; nf++) {
            int col = bcol + wn * 64 + nf * 8 + (lane & 3) * 2;
            *(float2*)&C[(size_t)row * N + col] =
                make_float2(acc[mf][nf][0], acc[mf][nf][1]);
            *(float2*)&C[(size_t)(row + 8) * N + col] =
                make_float2(acc[mf][nf][2], acc[mf][nf][3]);
        }
    }
}

// ---------------- fp32 -> (hi,lo) bf16 split, elementwise ------------------
__global__ void __launch_bounds__(256) split8_kernel(
    const float* __restrict__ x, __nv_bfloat16* __restrict__ hi,
    __nv_bfloat16* __restrict__ lo, int n)
{
    int i = (blockIdx.x * 256 + threadIdx.x) * 8;
    if (i >= n) return;
    float4 a = *(const float4*)(x + i);
    float4 b = *(const float4*)(x + i + 4);
    float v[8] = {a.x, a.y, a.z, a.w, b.x, b.y, b.z, b.w};
    uint32_t hp[4], lp[4];
    #pragma unroll
    for (int j = 0; j < 4; j++) {
        __nv_bfloat16 h0 = __float2bfloat16(v[2*j]);
        __nv_bfloat16 h1 = __float2bfloat16(v[2*j+1]);
        __nv_bfloat16 l0 = __float2bfloat16(v[2*j]   - __bfloat162float(h0));
        __nv_bfloat16 l1 = __float2bfloat16(v[2*j+1] - __bfloat162float(h1));
        __nv_bfloat162 hh = __halves2bfloat162(h0, h1);
        __nv_bfloat162 ll = __halves2bfloat162(l0, l1);
        hp[j] = *(uint32_t*)&hh;
        lp[j] = *(uint32_t*)&ll;
    }
    *(uint4*)(hi + i) = make_uint4(hp[0], hp[1], hp[2], hp[3]);
    *(uint4*)(lo + i) = make_uint4(lp[0], lp[1], lp[2], lp[3]);
}

// ---------------- W[K,N] -> Wt[N,K] with bf16 split ------------------------
__global__ void __launch_bounds__(256) transpose_split_kernel(
    const float* __restrict__ W, __nv_bfloat16* __restrict__ Thi,
    __nv_bfloat16* __restrict__ Tlo, int K, int N)
{
    __shared__ float tile[32][33];
    int k0 = blockIdx.y * 32, n0 = blockIdx.x * 32;
    int tx = threadIdx.x & 31, ty = threadIdx.x >> 5;   // 32 x 8
    #pragma unroll
    for (int j = ty; j < 32; j += 8)
        tile[j][tx] = W[(size_t)(k0 + j) * N + n0 + tx];
    __syncthreads();
    #pragma unroll
    for (int j = ty; j < 32; j += 8) {
        float v = tile[tx][j];                 // = W[k0+tx][n0+j]
        __nv_bfloat16 h = __float2bfloat16(v);
        __nv_bfloat16 l = __float2bfloat16(v - __bfloat162float(h));
        size_t o = (size_t)(n0 + j) * K + k0 + tx;
        Thi[o] = h;
        Tlo[o] = l;
    }
}

// ---------------- SGEMM (kept only for small dt projection) ----------------
__global__ void __launch_bounds__(256) sgemm_kernel(
    const float* __restrict__ A, const float* __restrict__ B,
    float* __restrict__ C, int M, int N, int Kdim)
{
    const int BM = 128, BN = 128, BK = 16, TM = 8, TN = 8;
    __shared__ float As[BM][BK];
    __shared__ float Bs[BK][BN];
    int tid = threadIdx.x;
    int brow = blockIdx.y * BM, bcol = blockIdx.x * BN;
    int tx = tid & 15, ty = tid >> 4;
    int trow = ty * TM, tcol = tx * TN;
    float acc[TM][TN];
    #pragma unroll
    for (int i = 0; i < TM; i++)
        #pragma unroll
        for (int j = 0; j < TN; j++) acc[i][j] = 0.f;
    for (int k0 = 0; k0 < Kdim; k0 += BK) {
        #pragma unroll
        for (int j = 0; j < 2; j++) {
            int i = tid + j * 256;
            int ar = i >> 2, ac4 = i & 3;
            *(float4*)&As[ar][ac4*4] =
                *(const float4*)&A[(size_t)(brow + ar) * Kdim + k0 + ac4*4];
        }
        #pragma unroll
        for (int j = 0; j < 2; j++) {
            int i = tid + j * 256;
            int br = i >> 5, bc4 = i & 31;
            int gcol = bcol + bc4*4;
            float4 bv = make_float4(0.f, 0.f, 0.f, 0.f);
            if (gcol < N) bv = *(const float4*)&B[(size_t)(k0 + br) * N + gcol];
            *(float4*)&Bs[br][bc4*4] = bv;
        }
        __syncthreads();
        #pragma unroll
        for (int kk = 0; kk < BK; kk++) {
            float a_frag[TM], b_frag[TN];
            #pragma unroll
            for (int i = 0; i < TM; i++) a_frag[i] = As[trow + i][kk];
            float4 b0 = *(float4*)&Bs[kk][tcol];
            float4 b1 = *(float4*)&Bs[kk][tcol + 4];
            b_frag[0]=b0.x; b_frag[1]=b0.y; b_frag[2]=b0.z; b_frag[3]=b0.w;
            b_frag[4]=b1.x; b_frag[5]=b1.y; b_frag[6]=b1.z; b_frag[7]=b1.w;
            #pragma unroll
            for (int i = 0; i < TM; i++)
                #pragma unroll
                for (int j = 0; j < TN; j++)
                    acc[i][j] = fmaf(a_frag[i], b_frag[j], acc[i][j]);
        }
        __syncthreads();
    }
    #pragma unroll
    for (int i = 0; i < TM; i++) {
        int row = brow + trow + i;
        #pragma unroll
        for (int j4 = 0; j4 < 2; j4++) {
            int col = bcol + tcol + j4*4;
            if (col < N)
                *(float4*)&C[(size_t)row * N + col] =
                    make_float4(acc[i][j4*4+0], acc[i][j4*4+1],
                                acc[i][j4*4+2], acc[i][j4*4+3]);
        }
    }
}

// ---------------- causal depthwise conv1d (K=4) + bias + silu --------------
__global__ void __launch_bounds__(256) conv_silu_kernel(
    const float* __restrict__ conv_w, const float* __restrict__ conv_b)
{
    int idx = blockIdx.x * 256 + threadIdx.x;
    int c  = idx % CONV_DIM;
    int bt = idx / CONV_DIM;
    int t  = bt & (LSEQ - 1);
    float acc = conv_b[c];
    #pragma unroll
    for (int k = 0; k < KCONV; k++) {
        int tt = t - (KCONV - 1) + k;
        if (tt >= 0)
            acc = fmaf(g_xBC[(size_t)(bt - (KCONV - 1) + k) * CONV_DIM + c],
                       conv_w[c * KCONV + k], acc);
    }
    g_xBCc[idx] = acc / (1.f + expf(-acc));
}

// ---------------- sequential SSM scan: one CTA per (b, head) ---------------
__global__ void __launch_bounds__(256) scan_kernel(
    const float* __restrict__ dt_bias, const float* __restrict__ A_log,
    const float* __restrict__ Dvec)
{
    int b = blockIdx.x >> 6;
    int h = blockIdx.x & 63;
    int tid = threadIdx.x;
    int p = tid >> 2, q = tid & 3;
    float state[32];
    #pragma unroll
    for (int i = 0; i < 32; i++) state[i] = 0.f;
    const float Ah   = -expf(A_log[h]);
    const float bias = dt_bias[h];
    const float Dh   = Dvec[h];
    __shared__ float sx[2][64];
    __shared__ float sBC[2][256];
    const float* xrow_base = g_xBCc + (size_t)b * LSEQ * CONV_DIM;
    const float* dt_base   = g_dt   + (size_t)b * LSEQ * NHEADS + h;
    float*       y_base    = g_y    + (size_t)b * LSEQ * INTER + h * PDIM;
    float rx = 0.f, rbc, rdt;
    {
        const float* row = xrow_base;
        if (tid < 64) rx = row[h * PDIM + tid];
        rbc = row[INTER + tid];
        rdt = dt_base[0];
    }
    for (int t = 0; t < LSEQ; t++) {
        int buf = t & 1;
        if (tid < 64) sx[buf][tid] = rx;
        sBC[buf][tid] = rbc;
        float dtv = rdt;
        __syncthreads();
        if (t + 1 < LSEQ) {
            const float* row = xrow_base + (size_t)(t + 1) * CONV_DIM;
            if (tid < 64) rx = row[h * PDIM + tid];
            rbc = row[INTER + tid];
            rdt = dt_base[(size_t)(t + 1) * NHEADS];
        }
        float xdt = dtv + bias;
        float sp  = (xdt < 10.f) ? log1pf(expf(xdt)) : xdt;
        float dA  = expf(sp * Ah);
        float xv  = sx[buf][p];
        float dtx = sp * xv;
        const float* Bp = sBC[buf];
        const float* Cp = sBC[buf] + 128;
        float accv = 0.f;
        #pragma unroll
        for (int i = 0; i < 32; i++) {
            int n = i * 4 + q;
            float s = fmaf(state[i], dA, dtx * Bp[n]);
            state[i] = s;
            accv = fmaf(s, Cp[n], accv);
        }
        accv += __shfl_xor_sync(0xffffffffu, accv, 1);
        accv += __shfl_xor_sync(0xffffffffu, accv, 2);
        if (q == 0)
            y_base[(size_t)t * INTER + p] = fmaf(Dh, xv, accv);
    }
}

// ---------------- gated RMSNorm + fused bf16 split -------------------------
__global__ void __launch_bounds__(256) norm_kernel(const float* __restrict__ norm_w)
{
    int tok = blockIdx.x;
    __shared__ float sh[INTER];
    __shared__ float sred[8];
    __shared__ float s_scale;
    const float* yrow = g_y    + (size_t)tok * INTER;
    const float* grow = g_gate + (size_t)tok * INTER;
    float ss = 0.f;
    for (int i = threadIdx.x; i < INTER; i += 256) {
        float g  = grow[i];
        float sg = g / (1.f + expf(-g));
        float hh = yrow[i] * sg;
        sh[i] = hh;
        ss = fmaf(hh, hh, ss);
    }
    #pragma unroll
    for (int o = 16; o; o >>= 1) ss += __shfl_xor_sync(0xffffffffu, ss, o);
    if ((threadIdx.x & 31) == 0) sred[threadIdx.x >> 5] = ss;
    __syncthreads();
    if (threadIdx.x == 0) {
        float tot = 0.f;
        #pragma unroll
        for (int j = 0; j < 8; j++) tot += sred[j];
        s_scale = rsqrtf(tot * (1.f / INTER) + EPS);
    }
    __syncthreads();
    float r = s_scale;
    for (int i = threadIdx.x; i < INTER; i += 256) {
        float val = sh[i] * r * norm_w[i];
        __nv_bfloat16 h = __float2bfloat16(val);
        __nv_bfloat16 l = __float2bfloat16(val - __bfloat162float(h));
        size_t o = (size_t)tok * INTER + i;
        g_norm_hi[o] = h;
        g_norm_lo[o] = l;
    }
}

// ---------------- launch ---------------------------------------------------
extern "C" void kernel_launch(void* const* d_in, const int* in_sizes, int n_in,
                              void* d_out, int out_size)
{
    const float* hs      = (const float*)d_in[0];
    const float* W_z     = (const float*)d_in[1];
    const float* W_xBC   = (const float*)d_in[2];
    const float* W_dt    = (const float*)d_in[3];
    const float* conv_w  = (const float*)d_in[4];
    const float* conv_b  = (const float*)d_in[5];
    const float* dt_bias = (const float*)d_in[6];
    const float* A_log   = (const float*)d_in[7];
    const float* Dv      = (const float*)d_in[8];
    const float* norm_w  = (const float*)d_in[9];
    const float* W_out   = (const float*)d_in[10];
    float* out = (float*)d_out;

    float *p_gate, *p_xBC, *p_dt;
    cudaGetSymbolAddress((void**)&p_gate, g_gate);
    cudaGetSymbolAddress((void**)&p_xBC,  g_xBC);
    cudaGetSymbolAddress((void**)&p_dt,   g_dt);
    __nv_bfloat16 *p_hs_hi, *p_hs_lo, *p_Wz_hi, *p_Wz_lo, *p_Wx_hi, *p_Wx_lo,
                  *p_Wo_hi, *p_Wo_lo, *p_nm_hi, *p_nm_lo;
    cudaGetSymbolAddress((void**)&p_hs_hi, g_hs_hi);
    cudaGetSymbolAddress((void**)&p_hs_lo, g_hs_lo);
    cudaGetSymbolAddress((void**)&p_Wz_hi, g_Wz_hi);
    cudaGetSymbolAddress((void**)&p_Wz_lo, g_Wz_lo);
    cudaGetSymbolAddress((void**)&p_Wx_hi, g_WxBC_hi);
    cudaGetSymbolAddress((void**)&p_Wx_lo, g_WxBC_lo);
    cudaGetSymbolAddress((void**)&p_Wo_hi, g_Wout_hi);
    cudaGetSymbolAddress((void**)&p_Wo_lo, g_Wout_lo);
    cudaGetSymbolAddress((void**)&p_nm_hi, g_norm_hi);
    cudaGetSymbolAddress((void**)&p_nm_lo, g_norm_lo);

    const int GSMEM = 2 * 4 * 16384;   // 131072 B: 2 stages x 4 tiles
    cudaFuncSetAttribute(gemm_mma, cudaFuncAttributeMaxDynamicSharedMemorySize, GSMEM);

    // 0) operand prep
    split8_kernel<<<(TOKENS*DMODEL/8 + 255)/256, 256>>>(hs, p_hs_hi, p_hs_lo, TOKENS*DMODEL);
    transpose_split_kernel<<<dim3(INTER/32, DMODEL/32), 256>>>(W_z, p_Wz_hi, p_Wz_lo, DMODEL, INTER);
    transpose_split_kernel<<<dim3(CONV_DIM/32, DMODEL/32), 256>>>(W_xBC, p_Wx_hi, p_Wx_lo, DMODEL, CONV_DIM);
    transpose_split_kernel<<<dim3(DMODEL/32, INTER/32), 256>>>(W_out, p_Wo_hi, p_Wo_lo, INTER, DMODEL);

    // 1) input projections (HMMA tensor cores) + small dt projection (SIMT)
    gemm_mma<<<dim3(INTER/128, TOKENS/128), 256, GSMEM>>>(
        p_hs_hi, p_hs_lo, p_Wz_hi, p_Wz_lo, p_gate, TOKENS, INTER, DMODEL);
    gemm_mma<<<dim3(CONV_DIM/128, TOKENS/128), 256, GSMEM>>>(
        p_hs_hi, p_hs_lo, p_Wx_hi, p_Wx_lo, p_xBC, TOKENS, CONV_DIM, DMODEL);
    sgemm_kernel<<<dim3(1, TOKENS/128), 256>>>(hs, W_dt, p_dt, TOKENS, NHEADS, DMODEL);

    // 2) causal conv + silu
    conv_silu_kernel<<<(TOKENS*CONV_DIM)/256, 256>>>(conv_w, conv_b);
    // 3) SSM scan
    scan_kernel<<<BSZ*NHEADS, 256>>>(dt_bias, A_log, Dv);
    // 4) gated RMSNorm (+ split for out-proj)
    norm_kernel<<<TOKENS, 256>>>(norm_w);
    // 5) output projection (HMMA tensor cores)
    gemm_mma<<<dim3(DMODEL/128, TOKENS/128), 256, GSMEM>>>(
        p_nm_hi, p_nm_lo, p_Wo_hi, p_Wo_lo, out, TOKENS, DMODEL, INTER);
}